// round 1
// baseline (speedup 1.0000x reference)
#include <cuda_runtime.h>
#include <cstdint>

#define BATCH 4
#define NPTS  16384
#define SPTS  2048
#define C1V   128
#define C2V   256
#define CIN   384
#define HV    256
#define BN_EPS 1e-5f

// Scratch (allocation-free: device globals)
__device__ float g_x [(size_t)BATCH * NPTS * CIN];   // concat(points1, interp)
__device__ float g_h1[(size_t)BATCH * NPTS * HV];    // hidden layer 1

__device__ __forceinline__ float finf() { return __int_as_float(0x7f800000); }

// ============================================================================
// Kernel 1: 3-NN + inverse-distance interpolation + concat -> g_x
// Grid: (BATCH, NPTS/32), Block: 128 threads (4 warps, 8 queries per warp)
// ============================================================================
__global__ __launch_bounds__(128) void knn_interp_kernel(
    const float* __restrict__ xyz1,     // [B, N, 3]
    const float* __restrict__ xyz2,     // [B, S, 3]
    const float* __restrict__ points1,  // [B, N, C1]
    const float* __restrict__ points2)  // [B, S, C2]
{
    __shared__ float sx[SPTS], sy[SPTS], sz[SPTS];
    const int b   = blockIdx.x;
    const int tid = threadIdx.x;

    const float* x2 = xyz2 + (size_t)b * SPTS * 3;
    for (int i = tid; i < SPTS; i += 128) {
        sx[i] = x2[i * 3 + 0];
        sy[i] = x2[i * 3 + 1];
        sz[i] = x2[i * 3 + 2];
    }
    __syncthreads();

    const int warp = tid >> 5;
    const int lane = tid & 31;

    for (int qi = 0; qi < 8; qi++) {
        const int n = blockIdx.y * 32 + warp * 8 + qi;
        const size_t row = (size_t)b * NPTS + n;
        const float qx = xyz1[row * 3 + 0];
        const float qy = xyz1[row * 3 + 1];
        const float qz = xyz1[row * 3 + 2];

        // local top-3 (ascending)
        float t0 = finf(), t1 = finf(), t2 = finf();
        int   i0 = -1,     i1 = -1,     i2 = -1;

        for (int s = lane; s < SPTS; s += 32) {
            float dx = sx[s] - qx;
            float dy = sy[s] - qy;
            float dz = sz[s] - qz;
            float d2 = fmaf(dx, dx, fmaf(dy, dy, dz * dz));
            if (d2 < t2) {
                if (d2 < t1) {
                    t2 = t1; i2 = i1;
                    if (d2 < t0) { t1 = t0; i1 = i0; t0 = d2; i0 = s; }
                    else         { t1 = d2; i1 = s; }
                } else { t2 = d2; i2 = s; }
            }
        }

        // warp-level merge: extract global 3 smallest via 3x argmin
        int ptr = 0;
        float bd[3]; int bi[3];
        #pragma unroll
        for (int r = 0; r < 3; r++) {
            float v  = (ptr == 0) ? t0 : ((ptr == 1) ? t1 : ((ptr == 2) ? t2 : finf()));
            int   vi = (ptr == 0) ? i0 : ((ptr == 1) ? i1 : ((ptr == 2) ? i2 : -1));
            #pragma unroll
            for (int off = 16; off > 0; off >>= 1) {
                float od = __shfl_down_sync(0xffffffffu, v,  off);
                int   oi = __shfl_down_sync(0xffffffffu, vi, off);
                if (od < v || (od == v && (unsigned)oi < (unsigned)vi)) { v = od; vi = oi; }
            }
            v  = __shfl_sync(0xffffffffu, v,  0);
            vi = __shfl_sync(0xffffffffu, vi, 0);
            bd[r] = v; bi[r] = vi;
            int cur = (ptr == 0) ? i0 : ((ptr == 1) ? i1 : ((ptr == 2) ? i2 : -2));
            if (cur == vi) ptr++;
        }

        // inverse-distance weights (identical on all lanes)
        float d0 = fmaxf(sqrtf(fmaxf(bd[0], 0.f)), 1e-10f);
        float d1 = fmaxf(sqrtf(fmaxf(bd[1], 0.f)), 1e-10f);
        float d2w = fmaxf(sqrtf(fmaxf(bd[2], 0.f)), 1e-10f);
        float w0 = 1.f / d0, w1 = 1.f / d1, w2 = 1.f / d2w;
        float ws = w0 + w1 + w2;
        w0 /= ws; w1 /= ws; w2 /= ws;

        // write concat row: [points1 | interp]
        const float4* p1 = (const float4*)(points1 + row * C1V);
        float4*       xo = (float4*)(g_x + row * CIN);
        xo[lane] = p1[lane];                       // 32 lanes * 16B = 128 floats

        const float4* r0 = (const float4*)(points2 + ((size_t)b * SPTS + bi[0]) * C2V);
        const float4* r1 = (const float4*)(points2 + ((size_t)b * SPTS + bi[1]) * C2V);
        const float4* r2 = (const float4*)(points2 + ((size_t)b * SPTS + bi[2]) * C2V);
        float4* xi = (float4*)(g_x + row * CIN + C1V);
        #pragma unroll
        for (int j = lane; j < C2V / 4; j += 32) {
            float4 a = r0[j], bb = r1[j], c = r2[j];
            float4 o;
            o.x = w0 * a.x + w1 * bb.x + w2 * c.x;
            o.y = w0 * a.y + w1 * bb.y + w2 * c.y;
            o.z = w0 * a.z + w1 * bb.z + w2 * c.z;
            o.w = w0 * a.w + w1 * bb.w + w2 * c.w;
            xi[j] = o;
        }
    }
}

// ============================================================================
// Kernel 2: SGEMM C[M,N] = A[M,K] * W[N,K]^T with fused BN(eval) + ReLU
// Block tile 128x128, K-tile 16, 256 threads, 8x8 register tiles.
// M, N, K all divisible by tile sizes (M=65536, N=256, K in {384,256}).
// ============================================================================
#define BM 128
#define BNT 128
#define BK 16

__global__ __launch_bounds__(256) void sgemm_bn_relu(
    const float* __restrict__ A,      // [M, K] row-major
    const float* __restrict__ W,      // [N, K] row-major
    float* __restrict__ C,            // [M, N] row-major
    const float* __restrict__ gamma,
    const float* __restrict__ beta,
    const float* __restrict__ rm,
    const float* __restrict__ rv,
    int M, int N, int K)
{
    __shared__ float As[BK][BM + 4];
    __shared__ float Bs[BK][BNT + 4];

    const int tid = threadIdx.x;
    const int bm = blockIdx.y * BM;
    const int bn = blockIdx.x * BNT;

    const int tr = (tid >> 4) * 8;   // row offset within tile, 0..120
    const int tc = (tid & 15) * 8;   // col offset within tile, 0..120

    const int arow = tid >> 2;        // 0..63 (loads rows arow and arow+64)
    const int acol = (tid & 3) * 4;   // 0,4,8,12

    float acc[8][8];
    #pragma unroll
    for (int i = 0; i < 8; i++)
        #pragma unroll
        for (int j = 0; j < 8; j++) acc[i][j] = 0.f;

    const float* Ap = A + (size_t)(bm + arow) * K + acol;
    const float* Bp = W + (size_t)(bn + arow) * K + acol;

    for (int k0 = 0; k0 < K; k0 += BK) {
        float4 a0 = *(const float4*)(Ap + k0);
        float4 a1 = *(const float4*)(Ap + k0 + (size_t)64 * K);
        float4 b0 = *(const float4*)(Bp + k0);
        float4 b1 = *(const float4*)(Bp + k0 + (size_t)64 * K);

        __syncthreads();   // previous iteration done reading smem
        As[acol + 0][arow] = a0.x;  As[acol + 1][arow] = a0.y;
        As[acol + 2][arow] = a0.z;  As[acol + 3][arow] = a0.w;
        As[acol + 0][arow + 64] = a1.x;  As[acol + 1][arow + 64] = a1.y;
        As[acol + 2][arow + 64] = a1.z;  As[acol + 3][arow + 64] = a1.w;
        Bs[acol + 0][arow] = b0.x;  Bs[acol + 1][arow] = b0.y;
        Bs[acol + 2][arow] = b0.z;  Bs[acol + 3][arow] = b0.w;
        Bs[acol + 0][arow + 64] = b1.x;  Bs[acol + 1][arow + 64] = b1.y;
        Bs[acol + 2][arow + 64] = b1.z;  Bs[acol + 3][arow + 64] = b1.w;
        __syncthreads();

        #pragma unroll
        for (int kk = 0; kk < BK; kk++) {
            float4 ra0 = *(const float4*)&As[kk][tr];
            float4 ra1 = *(const float4*)&As[kk][tr + 4];
            float4 rb0 = *(const float4*)&Bs[kk][tc];
            float4 rb1 = *(const float4*)&Bs[kk][tc + 4];
            float ra[8] = {ra0.x, ra0.y, ra0.z, ra0.w, ra1.x, ra1.y, ra1.z, ra1.w};
            float rb[8] = {rb0.x, rb0.y, rb0.z, rb0.w, rb1.x, rb1.y, rb1.z, rb1.w};
            #pragma unroll
            for (int i = 0; i < 8; i++)
                #pragma unroll
                for (int j = 0; j < 8; j++)
                    acc[i][j] = fmaf(ra[i], rb[j], acc[i][j]);
        }
    }

    // Fused eval-mode BatchNorm + ReLU epilogue
    float sc[8], sh[8];
    #pragma unroll
    for (int j = 0; j < 8; j++) {
        int nn = bn + tc + j;
        float s = gamma[nn] * rsqrtf(rv[nn] + BN_EPS);
        sc[j] = s;
        sh[j] = beta[nn] - rm[nn] * s;
    }
    #pragma unroll
    for (int i = 0; i < 8; i++) {
        float4 o0, o1;
        float v;
        v = fmaf(acc[i][0], sc[0], sh[0]); o0.x = fmaxf(v, 0.f);
        v = fmaf(acc[i][1], sc[1], sh[1]); o0.y = fmaxf(v, 0.f);
        v = fmaf(acc[i][2], sc[2], sh[2]); o0.z = fmaxf(v, 0.f);
        v = fmaf(acc[i][3], sc[3], sh[3]); o0.w = fmaxf(v, 0.f);
        v = fmaf(acc[i][4], sc[4], sh[4]); o1.x = fmaxf(v, 0.f);
        v = fmaf(acc[i][5], sc[5], sh[5]); o1.y = fmaxf(v, 0.f);
        v = fmaf(acc[i][6], sc[6], sh[6]); o1.z = fmaxf(v, 0.f);
        v = fmaf(acc[i][7], sc[7], sh[7]); o1.w = fmaxf(v, 0.f);
        float* cp = C + (size_t)(bm + tr + i) * N + bn + tc;
        *(float4*)(cp)     = o0;
        *(float4*)(cp + 4) = o1;
    }
}

// ============================================================================
extern "C" void kernel_launch(void* const* d_in, const int* in_sizes, int n_in,
                              void* d_out, int out_size)
{
    const float* xyz1    = (const float*)d_in[0];
    const float* xyz2    = (const float*)d_in[1];
    const float* points1 = (const float*)d_in[2];
    const float* points2 = (const float*)d_in[3];
    const float* W1      = (const float*)d_in[4];
    const float* gamma1  = (const float*)d_in[5];
    const float* beta1   = (const float*)d_in[6];
    const float* rm1     = (const float*)d_in[7];
    const float* rv1     = (const float*)d_in[8];
    const float* W2      = (const float*)d_in[9];
    const float* gamma2  = (const float*)d_in[10];
    const float* beta2   = (const float*)d_in[11];
    const float* rm2     = (const float*)d_in[12];
    const float* rv2     = (const float*)d_in[13];

    float* xptr;  cudaGetSymbolAddress((void**)&xptr,  g_x);
    float* h1ptr; cudaGetSymbolAddress((void**)&h1ptr, g_h1);

    const int M = BATCH * NPTS;   // 65536

    dim3 gKnn(BATCH, NPTS / 32), bKnn(128);
    knn_interp_kernel<<<gKnn, bKnn>>>(xyz1, xyz2, points1, points2);

    dim3 gG(HV / BNT, M / BM), bG(256);
    sgemm_bn_relu<<<gG, bG>>>(xptr, W1, h1ptr, gamma1, beta1, rm1, rv1, M, HV, CIN);
    sgemm_bn_relu<<<gG, bG>>>(h1ptr, W2, (float*)d_out, gamma2, beta2, rm2, rv2, M, HV, HV);
}

// round 5
// speedup vs baseline: 1.6989x; 1.6989x over previous
#include <cuda_runtime.h>
#include <cuda_bf16.h>
#include <cstdint>

#define BATCH 4
#define NPTS  16384
#define SPTS  2048
#define C1V   128
#define C2V   256
#define CIN   384
#define HV    256
#define BN_EPS 1e-5f
#define MTOT  (BATCH*NPTS)

// ---------------- scratch (device globals; no allocation) -------------------
__device__ __nv_bfloat16 g_xh[(size_t)MTOT * CIN];
__device__ __nv_bfloat16 g_xl[(size_t)MTOT * CIN];
__device__ __nv_bfloat16 g_h1h[(size_t)MTOT * HV];
__device__ __nv_bfloat16 g_h1l[(size_t)MTOT * HV];
__device__ __nv_bfloat16 g_W1h[HV * CIN], g_W1l[HV * CIN];
__device__ __nv_bfloat16 g_W2h[HV * HV],  g_W2l[HV * HV];

__device__ __forceinline__ float finf() { return __int_as_float(0x7f800000); }

__device__ __forceinline__ uint32_t smem_u32(const void* p) {
    uint32_t a;
    asm("{ .reg .u64 t; cvta.to.shared.u64 t, %1; cvt.u32.u64 %0, t; }" : "=r"(a) : "l"(p));
    return a;
}

// ---------------- mma.sync helpers (sm_80+ path, works under compute_100) ---
__device__ __forceinline__ void ldm_x4(uint32_t* r, uint32_t addr) {
    asm volatile("ldmatrix.sync.aligned.m8n8.x4.shared.b16 {%0,%1,%2,%3}, [%4];"
                 : "=r"(r[0]), "=r"(r[1]), "=r"(r[2]), "=r"(r[3]) : "r"(addr));
}
__device__ __forceinline__ void mma_bf16(float* c, const uint32_t* a, const uint32_t* b) {
    asm volatile("mma.sync.aligned.m16n8k16.row.col.f32.bf16.bf16.f32 "
                 "{%0,%1,%2,%3}, {%4,%5,%6,%7}, {%8,%9}, {%0,%1,%2,%3};"
                 : "+f"(c[0]), "+f"(c[1]), "+f"(c[2]), "+f"(c[3])
                 : "r"(a[0]), "r"(a[1]), "r"(a[2]), "r"(a[3]), "r"(b[0]), "r"(b[1]));
}

// ---------------- bf16 hi/lo split helpers ----------------------------------
__device__ __forceinline__ void split_store4(__nv_bfloat16* hp, __nv_bfloat16* lp, float4 v) {
    __nv_bfloat16 h0 = __float2bfloat16(v.x), h1 = __float2bfloat16(v.y);
    __nv_bfloat16 h2 = __float2bfloat16(v.z), h3 = __float2bfloat16(v.w);
    __nv_bfloat16 l0 = __float2bfloat16(v.x - __bfloat162float(h0));
    __nv_bfloat16 l1 = __float2bfloat16(v.y - __bfloat162float(h1));
    __nv_bfloat16 l2 = __float2bfloat16(v.z - __bfloat162float(h2));
    __nv_bfloat16 l3 = __float2bfloat16(v.w - __bfloat162float(h3));
    ((__nv_bfloat162*)hp)[0] = __halves2bfloat162(h0, h1);
    ((__nv_bfloat162*)hp)[1] = __halves2bfloat162(h2, h3);
    ((__nv_bfloat162*)lp)[0] = __halves2bfloat162(l0, l1);
    ((__nv_bfloat162*)lp)[1] = __halves2bfloat162(l2, l3);
}

// ---------------- weight split kernel ---------------------------------------
__global__ void split_weights_kernel(const float* __restrict__ W1,
                                     const float* __restrict__ W2)
{
    int i = blockIdx.x * 256 + threadIdx.x;
    if (i < HV * CIN) {
        float v = W1[i];
        __nv_bfloat16 h = __float2bfloat16(v);
        g_W1h[i] = h;
        g_W1l[i] = __float2bfloat16(v - __bfloat162float(h));
    }
    if (i < HV * HV) {
        float v = W2[i];
        __nv_bfloat16 h = __float2bfloat16(v);
        g_W2h[i] = h;
        g_W2l[i] = __float2bfloat16(v - __bfloat162float(h));
    }
}

// ============================================================================
// Kernel 1: 3-NN + inverse-distance interpolation + concat -> g_xh/g_xl
// ============================================================================
__global__ __launch_bounds__(128) void knn_interp_kernel(
    const float* __restrict__ xyz1,
    const float* __restrict__ xyz2,
    const float* __restrict__ points1,
    const float* __restrict__ points2)
{
    __shared__ float sx[SPTS], sy[SPTS], sz[SPTS];
    const int b   = blockIdx.x;
    const int tid = threadIdx.x;

    const float* x2 = xyz2 + (size_t)b * SPTS * 3;
    for (int i = tid; i < SPTS; i += 128) {
        sx[i] = x2[i * 3 + 0];
        sy[i] = x2[i * 3 + 1];
        sz[i] = x2[i * 3 + 2];
    }
    __syncthreads();

    const int warp = tid >> 5;
    const int lane = tid & 31;

    for (int qi = 0; qi < 8; qi++) {
        const int n = blockIdx.y * 32 + warp * 8 + qi;
        const size_t row = (size_t)b * NPTS + n;
        const float qx = xyz1[row * 3 + 0];
        const float qy = xyz1[row * 3 + 1];
        const float qz = xyz1[row * 3 + 2];

        float t0 = finf(), t1 = finf(), t2 = finf();
        int   i0 = -1,     i1 = -1,     i2 = -1;

        for (int s = lane; s < SPTS; s += 32) {
            float dx = sx[s] - qx;
            float dy = sy[s] - qy;
            float dz = sz[s] - qz;
            float d2 = fmaf(dx, dx, fmaf(dy, dy, dz * dz));
            if (d2 < t2) {
                if (d2 < t1) {
                    t2 = t1; i2 = i1;
                    if (d2 < t0) { t1 = t0; i1 = i0; t0 = d2; i0 = s; }
                    else         { t1 = d2; i1 = s; }
                } else { t2 = d2; i2 = s; }
            }
        }

        int ptr = 0;
        float bd[3]; int bi[3];
        #pragma unroll
        for (int r = 0; r < 3; r++) {
            float v  = (ptr == 0) ? t0 : ((ptr == 1) ? t1 : ((ptr == 2) ? t2 : finf()));
            int   vi = (ptr == 0) ? i0 : ((ptr == 1) ? i1 : ((ptr == 2) ? i2 : -1));
            #pragma unroll
            for (int off = 16; off > 0; off >>= 1) {
                float od = __shfl_down_sync(0xffffffffu, v,  off);
                int   oi = __shfl_down_sync(0xffffffffu, vi, off);
                if (od < v || (od == v && (unsigned)oi < (unsigned)vi)) { v = od; vi = oi; }
            }
            v  = __shfl_sync(0xffffffffu, v,  0);
            vi = __shfl_sync(0xffffffffu, vi, 0);
            bd[r] = v; bi[r] = vi;
            int cur = (ptr == 0) ? i0 : ((ptr == 1) ? i1 : ((ptr == 2) ? i2 : -2));
            if (cur == vi) ptr++;
        }

        float d0 = fmaxf(sqrtf(fmaxf(bd[0], 0.f)), 1e-10f);
        float d1 = fmaxf(sqrtf(fmaxf(bd[1], 0.f)), 1e-10f);
        float d2w = fmaxf(sqrtf(fmaxf(bd[2], 0.f)), 1e-10f);
        float w0 = 1.f / d0, w1 = 1.f / d1, w2 = 1.f / d2w;
        float ws = w0 + w1 + w2;
        w0 /= ws; w1 /= ws; w2 /= ws;

        const float4* p1 = (const float4*)(points1 + row * C1V);
        float4 pv = p1[lane];
        split_store4(g_xh + row * CIN + lane * 4, g_xl + row * CIN + lane * 4, pv);

        const float4* r0 = (const float4*)(points2 + ((size_t)b * SPTS + bi[0]) * C2V);
        const float4* r1 = (const float4*)(points2 + ((size_t)b * SPTS + bi[1]) * C2V);
        const float4* r2 = (const float4*)(points2 + ((size_t)b * SPTS + bi[2]) * C2V);
        #pragma unroll
        for (int j = lane; j < C2V / 4; j += 32) {
            float4 a = r0[j], bb = r1[j], c = r2[j];
            float4 o;
            o.x = w0 * a.x + w1 * bb.x + w2 * c.x;
            o.y = w0 * a.y + w1 * bb.y + w2 * c.y;
            o.z = w0 * a.z + w1 * bb.z + w2 * c.z;
            o.w = w0 * a.w + w1 * bb.w + w2 * c.w;
            split_store4(g_xh + row * CIN + C1V + j * 4,
                         g_xl + row * CIN + C1V + j * 4, o);
        }
    }
}

// ============================================================================
// Kernel 2: bf16 mma.sync GEMM  C[M,N] = A[M,K] * W[N,K]^T  (hi/lo 3 products)
// Block 128x128, BK=32, 256 threads = 8 warps (4x2), warp tile 32x64.
// Software prefetch: chunk c+1 global loads issued before chunk c MMAs.
// Fused BN(eval)+ReLU.  OUT_MODE 1: bf16 hi/lo, 2: fp32.
// ============================================================================
#define ASTR 40   // smem row stride in bf16 elems (80 bytes, conflict-free)

template<int KDIM, int OUT_MODE>
__global__ __launch_bounds__(256) void mma_gemm_bn_relu(
    const __nv_bfloat16* __restrict__ Ah, const __nv_bfloat16* __restrict__ Al,
    const __nv_bfloat16* __restrict__ Bh, const __nv_bfloat16* __restrict__ Bl,
    const float* __restrict__ gamma, const float* __restrict__ beta,
    const float* __restrict__ rm,    const float* __restrict__ rv,
    float* __restrict__ outf,
    __nv_bfloat16* __restrict__ outh, __nv_bfloat16* __restrict__ outl)
{
    __shared__ __nv_bfloat16 sAh[128 * ASTR], sAl[128 * ASTR];
    __shared__ __nv_bfloat16 sBh[128 * ASTR], sBl[128 * ASTR];

    const int tid    = threadIdx.x;
    const int lane   = tid & 31;
    const int wid    = tid >> 5;
    const int warp_m = wid >> 1;     // 0..3
    const int warp_n = wid & 1;      // 0..1
    const int m_base = blockIdx.x * 128;
    const int n_base = blockIdx.y * 128;

    float acc[2][8][4];
    #pragma unroll
    for (int i = 0; i < 2; i++)
        #pragma unroll
        for (int j = 0; j < 8; j++)
            #pragma unroll
            for (int q = 0; q < 4; q++) acc[i][j][q] = 0.f;

    // global load mapping: 256 threads, each loads one half-row (16 bf16) of
    // the 128x32 tile for all four arrays.
    const int lrow = tid >> 1;
    const int lcol = (tid & 1) * 16;
    const __nv_bfloat16* gAh = Ah + (size_t)(m_base + lrow) * KDIM + lcol;
    const __nv_bfloat16* gAl = Al + (size_t)(m_base + lrow) * KDIM + lcol;
    const __nv_bfloat16* gBh = Bh + (size_t)(n_base + lrow) * KDIM + lcol;
    const __nv_bfloat16* gBl = Bl + (size_t)(n_base + lrow) * KDIM + lcol;
    __nv_bfloat16* wAh = sAh + lrow * ASTR + lcol;
    __nv_bfloat16* wAl = sAl + lrow * ASTR + lcol;
    __nv_bfloat16* wBh = sBh + lrow * ASTR + lcol;
    __nv_bfloat16* wBl = sBl + lrow * ASTR + lcol;

    // ldmatrix fragment base addresses (bytes)
    const uint32_t aoff = (warp_m * 32 + (lane & 15)) * (ASTR * 2) + (lane >> 4) * 16;
    const uint32_t aAh = smem_u32(sAh) + aoff;
    const uint32_t aAl = smem_u32(sAl) + aoff;
    const uint32_t boff = (warp_n * 64 + (lane >> 4) * 8 + (lane & 7)) * (ASTR * 2)
                        + ((lane >> 3) & 1) * 16;
    const uint32_t aBh = smem_u32(sBh) + boff;
    const uint32_t aBl = smem_u32(sBl) + boff;

    const int CHUNKS = KDIM / 32;
    // prefetch chunk 0
    float4 vAh0 = *(const float4*)(gAh);
    float4 vAh1 = *(const float4*)(gAh + 8);
    float4 vAl0 = *(const float4*)(gAl);
    float4 vAl1 = *(const float4*)(gAl + 8);
    float4 vBh0 = *(const float4*)(gBh);
    float4 vBh1 = *(const float4*)(gBh + 8);
    float4 vBl0 = *(const float4*)(gBl);
    float4 vBl1 = *(const float4*)(gBl + 8);

    for (int c = 0; c < CHUNKS; c++) {
        __syncthreads();   // previous iteration's smem reads complete
        *(float4*)(wAh) = vAh0;  *(float4*)(wAh + 8) = vAh1;
        *(float4*)(wAl) = vAl0;  *(float4*)(wAl + 8) = vAl1;
        *(float4*)(wBh) = vBh0;  *(float4*)(wBh + 8) = vBh1;
        *(float4*)(wBl) = vBl0;  *(float4*)(wBl + 8) = vBl1;
        __syncthreads();

        // issue next chunk's global loads (latency hidden behind MMAs below)
        if (c + 1 < CHUNKS) {
            const int k1 = (c + 1) * 32;
            vAh0 = *(const float4*)(gAh + k1);
            vAh1 = *(const float4*)(gAh + k1 + 8);
            vAl0 = *(const float4*)(gAl + k1);
            vAl1 = *(const float4*)(gAl + k1 + 8);
            vBh0 = *(const float4*)(gBh + k1);
            vBh1 = *(const float4*)(gBh + k1 + 8);
            vBl0 = *(const float4*)(gBl + k1);
            vBl1 = *(const float4*)(gBl + k1 + 8);
        }

        #pragma unroll
        for (int ks = 0; ks < 2; ks++) {
            const uint32_t kso = ks * 32;
            uint32_t fah[2][4], fal[2][4];
            #pragma unroll
            for (int ma = 0; ma < 2; ma++) {
                ldm_x4(fah[ma], aAh + ma * 16 * (ASTR * 2) + kso);
                ldm_x4(fal[ma], aAl + ma * 16 * (ASTR * 2) + kso);
            }
            uint32_t fbh[4][4], fbl[4][4];
            #pragma unroll
            for (int np = 0; np < 4; np++) {
                ldm_x4(fbh[np], aBh + np * 16 * (ASTR * 2) + kso);
                ldm_x4(fbl[np], aBl + np * 16 * (ASTR * 2) + kso);
            }
            #pragma unroll
            for (int ma = 0; ma < 2; ma++)
                #pragma unroll
                for (int np = 0; np < 4; np++) {
                    mma_bf16(acc[ma][np * 2 + 0], fah[ma], &fbh[np][0]);
                    mma_bf16(acc[ma][np * 2 + 1], fah[ma], &fbh[np][2]);
                    mma_bf16(acc[ma][np * 2 + 0], fah[ma], &fbl[np][0]);
                    mma_bf16(acc[ma][np * 2 + 1], fah[ma], &fbl[np][2]);
                    mma_bf16(acc[ma][np * 2 + 0], fal[ma], &fbh[np][0]);
                    mma_bf16(acc[ma][np * 2 + 1], fal[ma], &fbh[np][2]);
                }
        }
    }

    // ---------------- epilogue: BN + ReLU ------------------------------------
    const int tq  = lane >> 2;          // 0..7
    const int tr2 = (lane & 3) * 2;     // 0,2,4,6
    float scv[16], shv[16];
    #pragma unroll
    for (int na = 0; na < 8; na++) {
        #pragma unroll
        for (int e = 0; e < 2; e++) {
            const int col = n_base + warp_n * 64 + na * 8 + tr2 + e;
            float s = gamma[col] * rsqrtf(rv[col] + BN_EPS);
            scv[na * 2 + e] = s;
            shv[na * 2 + e] = beta[col] - rm[col] * s;
        }
    }

    #pragma unroll
    for (int ma = 0; ma < 2; ma++) {
        #pragma unroll
        for (int half = 0; half < 2; half++) {
            const int row = m_base + warp_m * 32 + ma * 16 + half * 8 + tq;
            #pragma unroll
            for (int na = 0; na < 8; na++) {
                const int col = warp_n * 64 + na * 8 + tr2;
                float v0 = fmaxf(fmaf(acc[ma][na][half * 2 + 0],
                                      scv[na * 2 + 0], shv[na * 2 + 0]), 0.f);
                float v1 = fmaxf(fmaf(acc[ma][na][half * 2 + 1],
                                      scv[na * 2 + 1], shv[na * 2 + 1]), 0.f);
                const size_t o = (size_t)row * HV + n_base + col;
                if (OUT_MODE == 2) {
                    *(float2*)(outf + o) = make_float2(v0, v1);
                } else {
                    __nv_bfloat16 h0 = __float2bfloat16(v0);
                    __nv_bfloat16 h1 = __float2bfloat16(v1);
                    __nv_bfloat16 l0 = __float2bfloat16(v0 - __bfloat162float(h0));
                    __nv_bfloat16 l1 = __float2bfloat16(v1 - __bfloat162float(h1));
                    *(__nv_bfloat162*)(outh + o) = __halves2bfloat162(h0, h1);
                    *(__nv_bfloat162*)(outl + o) = __halves2bfloat162(l0, l1);
                }
            }
        }
    }
}

// ============================================================================
extern "C" void kernel_launch(void* const* d_in, const int* in_sizes, int n_in,
                              void* d_out, int out_size)
{
    const float* xyz1    = (const float*)d_in[0];
    const float* xyz2    = (const float*)d_in[1];
    const float* points1 = (const float*)d_in[2];
    const float* points2 = (const float*)d_in[3];
    const float* W1      = (const float*)d_in[4];
    const float* gamma1  = (const float*)d_in[5];
    const float* beta1   = (const float*)d_in[6];
    const float* rm1     = (const float*)d_in[7];
    const float* rv1     = (const float*)d_in[8];
    const float* W2      = (const float*)d_in[9];
    const float* gamma2  = (const float*)d_in[10];
    const float* beta2   = (const float*)d_in[11];
    const float* rm2     = (const float*)d_in[12];
    const float* rv2     = (const float*)d_in[13];

    __nv_bfloat16 *xh, *xl, *h1h, *h1l, *w1h, *w1l, *w2h, *w2l;
    cudaGetSymbolAddress((void**)&xh,  g_xh);
    cudaGetSymbolAddress((void**)&xl,  g_xl);
    cudaGetSymbolAddress((void**)&h1h, g_h1h);
    cudaGetSymbolAddress((void**)&h1l, g_h1l);
    cudaGetSymbolAddress((void**)&w1h, g_W1h);
    cudaGetSymbolAddress((void**)&w1l, g_W1l);
    cudaGetSymbolAddress((void**)&w2h, g_W2h);
    cudaGetSymbolAddress((void**)&w2l, g_W2l);

    split_weights_kernel<<<(HV * CIN + 255) / 256, 256>>>(W1, W2);

    dim3 gKnn(BATCH, NPTS / 32), bKnn(128);
    knn_interp_kernel<<<gKnn, bKnn>>>(xyz1, xyz2, points1, points2);

    dim3 gG(MTOT / 128, HV / 128), bG(256);
    mma_gemm_bn_relu<CIN, 1><<<gG, bG>>>(
        xh, xl, w1h, w1l, gamma1, beta1, rm1, rv1, nullptr, h1h, h1l);
    mma_gemm_bn_relu<HV, 2><<<gG, bG>>>(
        h1h, h1l, w2h, w2l, gamma2, beta2, rm2, rv2, (float*)d_out, nullptr, nullptr);
}

// round 7
// speedup vs baseline: 1.7724x; 1.0433x over previous
#include <cuda_runtime.h>
#include <cuda_bf16.h>
#include <cstdint>

#define BATCH 4
#define NPTS  16384
#define SPTS  2048
#define C1V   128
#define C2V   256
#define CIN   384
#define HV    256
#define BN_EPS 1e-5f
#define MTOT  (BATCH*NPTS)

// ---------------- scratch (device globals; no allocation) -------------------
__device__ __nv_bfloat16 g_xh[(size_t)MTOT * CIN];
__device__ __nv_bfloat16 g_xl[(size_t)MTOT * CIN];
__device__ __nv_bfloat16 g_h1h[(size_t)MTOT * HV];
__device__ __nv_bfloat16 g_h1l[(size_t)MTOT * HV];
__device__ __nv_bfloat16 g_W1h[HV * CIN], g_W1l[HV * CIN];
__device__ __nv_bfloat16 g_W2h[HV * HV],  g_W2l[HV * HV];

__device__ __forceinline__ float finf() { return __int_as_float(0x7f800000); }

__device__ __forceinline__ uint32_t smem_u32(const void* p) {
    uint32_t a;
    asm("{ .reg .u64 t; cvta.to.shared.u64 t, %1; cvt.u32.u64 %0, t; }" : "=r"(a) : "l"(p));
    return a;
}

// ---------------- mma.sync / cp.async helpers --------------------------------
__device__ __forceinline__ void ldm_x4(uint32_t* r, uint32_t addr) {
    asm volatile("ldmatrix.sync.aligned.m8n8.x4.shared.b16 {%0,%1,%2,%3}, [%4];"
                 : "=r"(r[0]), "=r"(r[1]), "=r"(r[2]), "=r"(r[3]) : "r"(addr));
}
__device__ __forceinline__ void mma_bf16(float* c, const uint32_t* a, const uint32_t* b) {
    asm volatile("mma.sync.aligned.m16n8k16.row.col.f32.bf16.bf16.f32 "
                 "{%0,%1,%2,%3}, {%4,%5,%6,%7}, {%8,%9}, {%0,%1,%2,%3};"
                 : "+f"(c[0]), "+f"(c[1]), "+f"(c[2]), "+f"(c[3])
                 : "r"(a[0]), "r"(a[1]), "r"(a[2]), "r"(a[3]), "r"(b[0]), "r"(b[1]));
}
__device__ __forceinline__ void cp16(uint32_t dst, const void* src) {
    asm volatile("cp.async.cg.shared.global [%0], [%1], 16;" :: "r"(dst), "l"(src));
}
#define CP_COMMIT() asm volatile("cp.async.commit_group;" ::: "memory")
#define CP_WAIT1()  asm volatile("cp.async.wait_group 1;" ::: "memory")
#define CP_WAIT0()  asm volatile("cp.async.wait_group 0;" ::: "memory")

// ---------------- bf16 hi/lo split helpers ----------------------------------
__device__ __forceinline__ void split_store4(__nv_bfloat16* hp, __nv_bfloat16* lp, float4 v) {
    __nv_bfloat16 h0 = __float2bfloat16(v.x), h1 = __float2bfloat16(v.y);
    __nv_bfloat16 h2 = __float2bfloat16(v.z), h3 = __float2bfloat16(v.w);
    __nv_bfloat16 l0 = __float2bfloat16(v.x - __bfloat162float(h0));
    __nv_bfloat16 l1 = __float2bfloat16(v.y - __bfloat162float(h1));
    __nv_bfloat16 l2 = __float2bfloat16(v.z - __bfloat162float(h2));
    __nv_bfloat16 l3 = __float2bfloat16(v.w - __bfloat162float(h3));
    ((__nv_bfloat162*)hp)[0] = __halves2bfloat162(h0, h1);
    ((__nv_bfloat162*)hp)[1] = __halves2bfloat162(h2, h3);
    ((__nv_bfloat162*)lp)[0] = __halves2bfloat162(l0, l1);
    ((__nv_bfloat162*)lp)[1] = __halves2bfloat162(l2, l3);
}

// ---------------- weight split kernel ---------------------------------------
__global__ void split_weights_kernel(const float* __restrict__ W1,
                                     const float* __restrict__ W2)
{
    int i = blockIdx.x * 256 + threadIdx.x;
    if (i < HV * CIN) {
        float v = W1[i];
        __nv_bfloat16 h = __float2bfloat16(v);
        g_W1h[i] = h;
        g_W1l[i] = __float2bfloat16(v - __bfloat162float(h));
    }
    if (i < HV * HV) {
        float v = W2[i];
        __nv_bfloat16 h = __float2bfloat16(v);
        g_W2h[i] = h;
        g_W2l[i] = __float2bfloat16(v - __bfloat162float(h));
    }
}

// ============================================================================
// Kernel 1: 3-NN + interpolation + concat -> g_xh/g_xl
// smem holds float4(px,py,pz,|p|^2); candidate metric d2' = |p|^2 - 2 q.p
// (d2 = d2' + |q|^2, constant per query -> same argmin ordering).
// ============================================================================
__global__ __launch_bounds__(128) void knn_interp_kernel(
    const float* __restrict__ xyz1,
    const float* __restrict__ xyz2,
    const float* __restrict__ points1,
    const float* __restrict__ points2)
{
    __shared__ float4 sp[SPTS];
    const int b   = blockIdx.x;
    const int tid = threadIdx.x;

    const float* x2 = xyz2 + (size_t)b * SPTS * 3;
    for (int i = tid; i < SPTS; i += 128) {
        float px = x2[i * 3 + 0];
        float py = x2[i * 3 + 1];
        float pz = x2[i * 3 + 2];
        sp[i] = make_float4(px, py, pz, fmaf(px, px, fmaf(py, py, pz * pz)));
    }
    __syncthreads();

    const int warp = tid >> 5;
    const int lane = tid & 31;

    for (int qi = 0; qi < 8; qi++) {
        const int n = blockIdx.y * 32 + warp * 8 + qi;
        const size_t row = (size_t)b * NPTS + n;
        const float qx = xyz1[row * 3 + 0];
        const float qy = xyz1[row * 3 + 1];
        const float qz = xyz1[row * 3 + 2];
        const float m2x = -2.f * qx, m2y = -2.f * qy, m2z = -2.f * qz;
        const float qq  = fmaf(qx, qx, fmaf(qy, qy, qz * qz));

        float t0 = finf(), t1 = finf(), t2 = finf();
        int   i0 = -1,     i1 = -1,     i2 = -1;

        #pragma unroll 4
        for (int s = lane; s < SPTS; s += 32) {
            float4 p = sp[s];
            float d2 = fmaf(m2x, p.x, fmaf(m2y, p.y, fmaf(m2z, p.z, p.w)));
            if (d2 < t2) {
                if (d2 < t1) {
                    t2 = t1; i2 = i1;
                    if (d2 < t0) { t1 = t0; i1 = i0; t0 = d2; i0 = s; }
                    else         { t1 = d2; i1 = s; }
                } else { t2 = d2; i2 = s; }
            }
        }

        int ptr = 0;
        float bd[3]; int bi[3];
        #pragma unroll
        for (int r = 0; r < 3; r++) {
            float v  = (ptr == 0) ? t0 : ((ptr == 1) ? t1 : ((ptr == 2) ? t2 : finf()));
            int   vi = (ptr == 0) ? i0 : ((ptr == 1) ? i1 : ((ptr == 2) ? i2 : -1));
            #pragma unroll
            for (int off = 16; off > 0; off >>= 1) {
                float od = __shfl_down_sync(0xffffffffu, v,  off);
                int   oi = __shfl_down_sync(0xffffffffu, vi, off);
                if (od < v || (od == v && (unsigned)oi < (unsigned)vi)) { v = od; vi = oi; }
            }
            v  = __shfl_sync(0xffffffffu, v,  0);
            vi = __shfl_sync(0xffffffffu, vi, 0);
            bd[r] = v; bi[r] = vi;
            int cur = (ptr == 0) ? i0 : ((ptr == 1) ? i1 : ((ptr == 2) ? i2 : -2));
            if (cur == vi) ptr++;
        }

        float d0 = fmaxf(sqrtf(fmaxf(bd[0] + qq, 0.f)), 1e-10f);
        float d1 = fmaxf(sqrtf(fmaxf(bd[1] + qq, 0.f)), 1e-10f);
        float d2w = fmaxf(sqrtf(fmaxf(bd[2] + qq, 0.f)), 1e-10f);
        float w0 = 1.f / d0, w1 = 1.f / d1, w2 = 1.f / d2w;
        float ws = w0 + w1 + w2;
        w0 /= ws; w1 /= ws; w2 /= ws;

        const float4* p1 = (const float4*)(points1 + row * C1V);
        float4 pv = p1[lane];
        split_store4(g_xh + row * CIN + lane * 4, g_xl + row * CIN + lane * 4, pv);

        const float4* r0 = (const float4*)(points2 + ((size_t)b * SPTS + bi[0]) * C2V);
        const float4* r1 = (const float4*)(points2 + ((size_t)b * SPTS + bi[1]) * C2V);
        const float4* r2 = (const float4*)(points2 + ((size_t)b * SPTS + bi[2]) * C2V);
        #pragma unroll
        for (int j = lane; j < C2V / 4; j += 32) {
            float4 a = r0[j], bb = r1[j], c = r2[j];
            float4 o;
            o.x = w0 * a.x + w1 * bb.x + w2 * c.x;
            o.y = w0 * a.y + w1 * bb.y + w2 * c.y;
            o.z = w0 * a.z + w1 * bb.z + w2 * c.z;
            o.w = w0 * a.w + w1 * bb.w + w2 * c.w;
            split_store4(g_xh + row * CIN + C1V + j * 4,
                         g_xl + row * CIN + C1V + j * 4, o);
        }
    }
}

// ============================================================================
// Kernel 2: bf16 mma.sync GEMM, 2-stage cp.async double buffer, 2 CTAs/SM.
// Block 128x128, BK=32, 256 threads = 8 warps (4x2), warp tile 32x64.
// Each thread copies 16 elems (2 x cp16) per array per chunk.
// ============================================================================
#define ASTR 40                      // smem row stride in bf16 (80B, conflict-free)
#define ARR_BYTES (128 * ASTR * 2)   // 10240 B per array
#define STAGE_BYTES (4 * ARR_BYTES)  // 40960 B per stage
#define GSMEM_TOTAL (2 * STAGE_BYTES)

template<int KDIM, int OUT_MODE>
__global__ __launch_bounds__(256, 2) void mma_gemm_bn_relu(
    const __nv_bfloat16* __restrict__ Ah, const __nv_bfloat16* __restrict__ Al,
    const __nv_bfloat16* __restrict__ Bh, const __nv_bfloat16* __restrict__ Bl,
    const float* __restrict__ gamma, const float* __restrict__ beta,
    const float* __restrict__ rm,    const float* __restrict__ rv,
    float* __restrict__ outf,
    __nv_bfloat16* __restrict__ outh, __nv_bfloat16* __restrict__ outl)
{
    extern __shared__ char dsm[];
    const uint32_t sbase = smem_u32(dsm);

    const int tid    = threadIdx.x;
    const int lane   = tid & 31;
    const int wid    = tid >> 5;
    const int warp_m = wid >> 1;
    const int warp_n = wid & 1;
    const int m_base = blockIdx.x * 128;
    const int n_base = blockIdx.y * 128;

    float acc[2][8][4];
    #pragma unroll
    for (int i = 0; i < 2; i++)
        #pragma unroll
        for (int j = 0; j < 8; j++)
            #pragma unroll
            for (int q = 0; q < 4; q++) acc[i][j][q] = 0.f;

    // global load mapping: each thread copies 16 bf16 (two cp16) per array.
    // lrow 0..127 (2 threads per row), lcol in {0,16} elems.
    const int lrow = tid >> 1;
    const int lcol = (tid & 1) * 16;
    const __nv_bfloat16* gsrc[4] = {
        Ah + (size_t)(m_base + lrow) * KDIM + lcol,
        Al + (size_t)(m_base + lrow) * KDIM + lcol,
        Bh + (size_t)(n_base + lrow) * KDIM + lcol,
        Bl + (size_t)(n_base + lrow) * KDIM + lcol };
    const uint32_t woff = lrow * (ASTR * 2) + lcol * 2;  // byte offset in array

    // ldmatrix fragment offsets (bytes, within a stage)
    const uint32_t aoff = (warp_m * 32 + (lane & 15)) * (ASTR * 2) + (lane >> 4) * 16;
    const uint32_t boff = (warp_n * 64 + (lane >> 4) * 8 + (lane & 7)) * (ASTR * 2)
                        + ((lane >> 3) & 1) * 16;

    const int CHUNKS = KDIM / 32;

    // prologue: stage 0 <- chunk 0
    #pragma unroll
    for (int a = 0; a < 4; a++) {
        cp16(sbase + a * ARR_BYTES + woff,      gsrc[a]);
        cp16(sbase + a * ARR_BYTES + woff + 16, gsrc[a] + 8);
    }
    CP_COMMIT();

    for (int c = 0; c < CHUNKS; c++) {
        const uint32_t st = (uint32_t)(c & 1) * STAGE_BYTES;
        if (c + 1 < CHUNKS) {
            const uint32_t st1 = (uint32_t)((c + 1) & 1) * STAGE_BYTES;
            const int k1 = (c + 1) * 32;
            #pragma unroll
            for (int a = 0; a < 4; a++) {
                cp16(sbase + st1 + a * ARR_BYTES + woff,      gsrc[a] + k1);
                cp16(sbase + st1 + a * ARR_BYTES + woff + 16, gsrc[a] + k1 + 8);
            }
            CP_COMMIT();
            CP_WAIT1();
        } else {
            CP_WAIT0();
        }
        __syncthreads();

        const uint32_t aAh = sbase + st + 0 * ARR_BYTES + aoff;
        const uint32_t aAl = sbase + st + 1 * ARR_BYTES + aoff;
        const uint32_t aBh = sbase + st + 2 * ARR_BYTES + boff;
        const uint32_t aBl = sbase + st + 3 * ARR_BYTES + boff;

        #pragma unroll
        for (int ks = 0; ks < 2; ks++) {
            const uint32_t kso = ks * 32;
            uint32_t fah[2][4], fal[2][4];
            #pragma unroll
            for (int ma = 0; ma < 2; ma++) {
                ldm_x4(fah[ma], aAh + ma * 16 * (ASTR * 2) + kso);
                ldm_x4(fal[ma], aAl + ma * 16 * (ASTR * 2) + kso);
            }
            #pragma unroll
            for (int np = 0; np < 4; np++) {
                uint32_t fbh[4], fbl[4];
                ldm_x4(fbh, aBh + np * 16 * (ASTR * 2) + kso);
                ldm_x4(fbl, aBl + np * 16 * (ASTR * 2) + kso);
                #pragma unroll
                for (int ma = 0; ma < 2; ma++) {
                    mma_bf16(acc[ma][np * 2 + 0], fah[ma], &fbh[0]);
                    mma_bf16(acc[ma][np * 2 + 1], fah[ma], &fbh[2]);
                    mma_bf16(acc[ma][np * 2 + 0], fah[ma], &fbl[0]);
                    mma_bf16(acc[ma][np * 2 + 1], fah[ma], &fbl[2]);
                    mma_bf16(acc[ma][np * 2 + 0], fal[ma], &fbh[0]);
                    mma_bf16(acc[ma][np * 2 + 1], fal[ma], &fbh[2]);
                }
            }
        }
        __syncthreads();   // all warps done reading stage st before it is refilled
    }

    // ---------------- epilogue: BN + ReLU ------------------------------------
    const int tq  = lane >> 2;
    const int tr2 = (lane & 3) * 2;
    float scv[16], shv[16];
    #pragma unroll
    for (int na = 0; na < 8; na++) {
        #pragma unroll
        for (int e = 0; e < 2; e++) {
            const int col = n_base + warp_n * 64 + na * 8 + tr2 + e;
            float s = gamma[col] * rsqrtf(rv[col] + BN_EPS);
            scv[na * 2 + e] = s;
            shv[na * 2 + e] = beta[col] - rm[col] * s;
        }
    }

    #pragma unroll
    for (int ma = 0; ma < 2; ma++) {
        #pragma unroll
        for (int half = 0; half < 2; half++) {
            const int row = m_base + warp_m * 32 + ma * 16 + half * 8 + tq;
            #pragma unroll
            for (int na = 0; na < 8; na++) {
                const int col = warp_n * 64 + na * 8 + tr2;
                float v0 = fmaxf(fmaf(acc[ma][na][half * 2 + 0],
                                      scv[na * 2 + 0], shv[na * 2 + 0]), 0.f);
                float v1 = fmaxf(fmaf(acc[ma][na][half * 2 + 1],
                                      scv[na * 2 + 1], shv[na * 2 + 1]), 0.f);
                const size_t o = (size_t)row * HV + n_base + col;
                if (OUT_MODE == 2) {
                    *(float2*)(outf + o) = make_float2(v0, v1);
                } else {
                    __nv_bfloat16 h0 = __float2bfloat16(v0);
                    __nv_bfloat16 h1 = __float2bfloat16(v1);
                    __nv_bfloat16 l0 = __float2bfloat16(v0 - __bfloat162float(h0));
                    __nv_bfloat16 l1 = __float2bfloat16(v1 - __bfloat162float(h1));
                    *(__nv_bfloat162*)(outh + o) = __halves2bfloat162(h0, h1);
                    *(__nv_bfloat162*)(outl + o) = __halves2bfloat162(l0, l1);
                }
            }
        }
    }
}

// ============================================================================
extern "C" void kernel_launch(void* const* d_in, const int* in_sizes, int n_in,
                              void* d_out, int out_size)
{
    const float* xyz1    = (const float*)d_in[0];
    const float* xyz2    = (const float*)d_in[1];
    const float* points1 = (const float*)d_in[2];
    const float* points2 = (const float*)d_in[3];
    const float* W1      = (const float*)d_in[4];
    const float* gamma1  = (const float*)d_in[5];
    const float* beta1   = (const float*)d_in[6];
    const float* rm1     = (const float*)d_in[7];
    const float* rv1     = (const float*)d_in[8];
    const float* W2      = (const float*)d_in[9];
    const float* gamma2  = (const float*)d_in[10];
    const float* beta2   = (const float*)d_in[11];
    const float* rm2     = (const float*)d_in[12];
    const float* rv2     = (const float*)d_in[13];

    __nv_bfloat16 *xh, *xl, *h1h, *h1l, *w1h, *w1l, *w2h, *w2l;
    cudaGetSymbolAddress((void**)&xh,  g_xh);
    cudaGetSymbolAddress((void**)&xl,  g_xl);
    cudaGetSymbolAddress((void**)&h1h, g_h1h);
    cudaGetSymbolAddress((void**)&h1l, g_h1l);
    cudaGetSymbolAddress((void**)&w1h, g_W1h);
    cudaGetSymbolAddress((void**)&w1l, g_W1l);
    cudaGetSymbolAddress((void**)&w2h, g_W2h);
    cudaGetSymbolAddress((void**)&w2l, g_W2l);

    cudaFuncSetAttribute(mma_gemm_bn_relu<CIN, 1>,
                         cudaFuncAttributeMaxDynamicSharedMemorySize, GSMEM_TOTAL);
    cudaFuncSetAttribute(mma_gemm_bn_relu<HV, 2>,
                         cudaFuncAttributeMaxDynamicSharedMemorySize, GSMEM_TOTAL);

    split_weights_kernel<<<(HV * CIN + 255) / 256, 256>>>(W1, W2);

    dim3 gKnn(BATCH, NPTS / 32), bKnn(128);
    knn_interp_kernel<<<gKnn, bKnn>>>(xyz1, xyz2, points1, points2);

    dim3 gG(MTOT / 128, HV / 128), bG(256);
    mma_gemm_bn_relu<CIN, 1><<<gG, bG, GSMEM_TOTAL>>>(
        xh, xl, w1h, w1l, gamma1, beta1, rm1, rv1, nullptr, h1h, h1l);
    mma_gemm_bn_relu<HV, 2><<<gG, bG, GSMEM_TOTAL>>>(
        h1h, h1l, w2h, w2l, gamma2, beta2, rm2, rv2, (float*)d_out, nullptr, nullptr);
}